// round 2
// baseline (speedup 1.0000x reference)
#include <cuda_runtime.h>
#include <cuda_bf16.h>
#include <cstdint>

// ============================================================
// SparseModel: 32 independent MLPs (64 -> 128 -> 128 -> 128 -> 1, swish)
// mma.sync (HMMA bf16) kernel, split-bf16 3-pass for fp32-grade accuracy.
// (tcgen05 unavailable: harness PTX target is sm_103, not sm_103a)
// ============================================================

#define THREADS 256
#define TILE_M 128
#define GROUPS 32            // 32768 rows / (32 groups * 128) = 8 tiles per CTA
#define TILES_PER_CTA 8

// ---- smem layout (bytes; tiles 1024-aligned) ----
static constexpr int SM_ACT_H = 0;        // A tile hi [128 x 128 bf16]
static constexpr int SM_ACT_L = 32768;    // A tile lo
static constexpr int SM_W1_H  = 65536;    // W1 hi [128n x 64k bf16]
static constexpr int SM_W1_L  = 81920;
static constexpr int SM_WH_H0 = 98304;    // Wh0 hi [128n x 128k bf16]
static constexpr int SM_WH_L0 = 131072;
static constexpr int SM_WH_H1 = 163840;
static constexpr int SM_WH_L1 = 196608;
static constexpr int SM_PART  = 229376;         // 128 floats (head partials)
static constexpr int SM_BIAS  = SM_PART + 512;  // 3 x 128 floats
static constexpr int SM_WO    = SM_BIAS + 1536; // 128 floats
static constexpr int SM_TOTAL = SM_WO + 512;    // 231936 <= 232448

// ---- helpers ----
__device__ __forceinline__ uint32_t smem_to_u32(const void* p) {
    uint32_t a;
    asm("{ .reg .u64 t; cvta.to.shared.u64 t, %1; cvt.u32.u64 %0, t; }" : "=r"(a) : "l"(p));
    return a;
}
// SW128 swizzle on a [128 rows x K] bf16 K-major tile with 8-row x 128B atoms.
__device__ __forceinline__ uint32_t swz(uint32_t b) { return b ^ ((b >> 3) & 0x70u); }
__device__ __forceinline__ uint32_t toff(int r, int k) {
    return (uint32_t)(((((k >> 6) << 4) + (r >> 3)) << 10) | ((r & 7) << 7) | ((k & 63) << 1));
}

#define LDSM_X4(r, addr) \
    asm volatile("ldmatrix.sync.aligned.m8n8.x4.shared.b16 {%0,%1,%2,%3}, [%4];" \
        : "=r"((r)[0]), "=r"((r)[1]), "=r"((r)[2]), "=r"((r)[3]) : "r"(addr))
#define LDSM_X2(r, addr) \
    asm volatile("ldmatrix.sync.aligned.m8n8.x2.shared.b16 {%0,%1}, [%2];" \
        : "=r"((r)[0]), "=r"((r)[1]) : "r"(addr))
#define MMA16816(d, a, b) \
    asm volatile("mma.sync.aligned.m16n8k16.row.col.f32.bf16.bf16.f32 " \
        "{%0,%1,%2,%3}, {%4,%5,%6,%7}, {%8,%9}, {%0,%1,%2,%3};" \
        : "+f"((d)[0]), "+f"((d)[1]), "+f"((d)[2]), "+f"((d)[3]) \
        : "r"((a)[0]), "r"((a)[1]), "r"((a)[2]), "r"((a)[3]), "r"((b)[0]), "r"((b)[1]))

__device__ __forceinline__ float swishf(float v) {
    return __fdividef(v, 1.0f + __expf(-v));
}
__device__ __forceinline__ uint32_t pack2(__nv_bfloat16 a, __nv_bfloat16 b) {
    __nv_bfloat162 t = __halves2bfloat162(a, b);
    return *reinterpret_cast<uint32_t*>(&t);
}

__global__ void __launch_bounds__(THREADS, 1)
mlp_fused_kernel(const float* __restrict__ x,  const float* __restrict__ W1,
                 const float* __restrict__ b1, const float* __restrict__ Wh,
                 const float* __restrict__ bh, const float* __restrict__ Wo,
                 const float* __restrict__ bo, float* __restrict__ out)
{
    extern __shared__ char smc[];
    const uint32_t smb = smem_to_u32(smc);
    const int tid = threadIdx.x;
    const int wid = tid >> 5;
    const int lane = tid & 31;
    const int o = blockIdx.x & 31;       // subnet
    const int g = blockIdx.x >> 5;       // row group

    // ---- load + split weights into smem (once per CTA) ----
    {
        const float* W1p = W1 + o * 64 * 128;
        for (int idx = tid; idx < 64 * 128; idx += THREADS) {
            int k = idx >> 7, j = idx & 127;   // W1[o][k][j] -> B[n=j][k]
            float w = W1p[idx];
            __nv_bfloat16 h = __float2bfloat16(w);
            float lo = w - __bfloat162float(h);
            uint32_t off = swz(toff(j, k));
            *reinterpret_cast<__nv_bfloat16*>(smc + SM_W1_H + off) = h;
            *reinterpret_cast<__nv_bfloat16*>(smc + SM_W1_L + off) = __float2bfloat16(lo);
        }
        #pragma unroll
        for (int l = 0; l < 2; l++) {
            const float* Wp = Wh + ((size_t)l * 32 + o) * 128 * 128;
            const int hB = l ? SM_WH_H1 : SM_WH_H0;
            const int lB = l ? SM_WH_L1 : SM_WH_L0;
            for (int idx = tid; idx < 128 * 128; idx += THREADS) {
                int k = idx >> 7, j = idx & 127;
                float w = Wp[idx];
                __nv_bfloat16 h = __float2bfloat16(w);
                float lo = w - __bfloat162float(h);
                uint32_t off = swz(toff(j, k));
                *reinterpret_cast<__nv_bfloat16*>(smc + hB + off) = h;
                *reinterpret_cast<__nv_bfloat16*>(smc + lB + off) = __float2bfloat16(lo);
            }
        }
        for (int j = tid; j < 128; j += THREADS) {
            reinterpret_cast<float*>(smc + SM_BIAS)[j]       = b1[o * 128 + j];
            reinterpret_cast<float*>(smc + SM_BIAS)[128 + j] = bh[(size_t)o * 128 + j];
            reinterpret_cast<float*>(smc + SM_BIAS)[256 + j] = bh[((size_t)32 + o) * 128 + j];
            reinterpret_cast<float*>(smc + SM_WO)[j]         = Wo[o * 128 + j];
        }
    }
    __syncthreads();

    const float bo_v   = bo[o];
    const float* sbias = reinterpret_cast<const float*>(smc + SM_BIAS);
    const float* sWo   = reinterpret_cast<const float*>(smc + SM_WO);
    float* sPart       = reinterpret_cast<float*>(smc + SM_PART);

    // warp tiling: 4(m) x 2(n); warp tile = 32 rows x 64 cols
    const int wm = wid & 3;
    const int wn = wid >> 2;

    // ---- ldmatrix lane addressing ----
    // A frags (16x16): lanes 0-7 rows+0/k+0, 8-15 rows+8/k+0, 16-23 rows+0/k+8, 24-31 rows+8/k+8
    const int ra0 = wm * 32 + ((lane >> 3) & 1) * 8 + (lane & 7);   // mt=0 row
    const uint32_t aP0 = (uint32_t)(((ra0 >> 3) << 10) | ((ra0 & 7) << 7));
    const uint32_t aP1 = aP0 + (2u << 10);                          // mt=1: +16 rows = +2 atoms
    const uint32_t aX  = (uint32_t)((lane & 7) << 4);
    const int ka = (lane >> 4) * 8;                                  // A k sub-offset
    // B frags (n-major [n][k]): lanes 0-7 -> n rows / k+0, lanes 8-15 -> n rows / k+8
    const int lb = lane & 15;
    const uint32_t bRow = (uint32_t)(((wn * 8) << 10) | ((lb & 7) << 7));
    const uint32_t bX   = (uint32_t)((lb & 7) << 4);
    const int kb = ((lb >> 3) & 1) * 8;

    const uint32_t actH = smb + SM_ACT_H, actL = smb + SM_ACT_L;
    const uint32_t bHl[3] = { smb + SM_W1_H, smb + SM_WH_H0, smb + SM_WH_H1 };
    const uint32_t bLl[3] = { smb + SM_W1_L, smb + SM_WH_L0, smb + SM_WH_L1 };

    for (int t = 0; t < TILES_PER_CTA; t++) {
        const int m0 = (g * TILES_PER_CTA + t) * TILE_M;
        if (tid < 128) sPart[tid] = 0.0f;

        // ---- stage X tile: [128 x 64] fp32 -> split bf16 hi/lo, swizzled ----
        {
            const int r  = tid >> 1;
            const int kbx = (tid & 1) << 5;
            const float4* xp = reinterpret_cast<const float4*>(x + (size_t)(m0 + r) * 64 + kbx);
            #pragma unroll
            for (int q = 0; q < 8; q++) {
                float4 v = xp[q];
                __nv_bfloat162 h01 = __floats2bfloat162_rn(v.x, v.y);
                __nv_bfloat162 h23 = __floats2bfloat162_rn(v.z, v.w);
                float l0 = v.x - __bfloat162float(__low2bfloat16(h01));
                float l1 = v.y - __bfloat162float(__high2bfloat16(h01));
                float l2 = v.z - __bfloat162float(__low2bfloat16(h23));
                float l3 = v.w - __bfloat162float(__high2bfloat16(h23));
                uint32_t off0 = swz(toff(r, kbx + 4 * q));
                uint32_t off1 = swz(toff(r, kbx + 4 * q + 2));
                *reinterpret_cast<uint32_t*>(smc + SM_ACT_H + off0) = *reinterpret_cast<uint32_t*>(&h01);
                *reinterpret_cast<uint32_t*>(smc + SM_ACT_H + off1) = *reinterpret_cast<uint32_t*>(&h23);
                __nv_bfloat162 g01 = __floats2bfloat162_rn(l0, l1);
                __nv_bfloat162 g23 = __floats2bfloat162_rn(l2, l3);
                *reinterpret_cast<uint32_t*>(smc + SM_ACT_L + off0) = *reinterpret_cast<uint32_t*>(&g01);
                *reinterpret_cast<uint32_t*>(smc + SM_ACT_L + off1) = *reinterpret_cast<uint32_t*>(&g23);
            }
        }
        __syncthreads();

        // ---- 3 layers ----
        for (int l = 0; l < 3; l++) {
            const int nch = (l == 0) ? 4 : 8;
            const uint32_t bH = bHl[l], bL = bLl[l];

            float acc[2][8][4];
            #pragma unroll
            for (int mt = 0; mt < 2; mt++)
                #pragma unroll
                for (int nt = 0; nt < 8; nt++)
                    #pragma unroll
                    for (int e = 0; e < 4; e++) acc[mt][nt][e] = 0.0f;

            for (int c = 0; c < nch; ++c) {
                const uint32_t kA  = (uint32_t)(c * 16 + ka);
                const uint32_t kxA = ((kA >> 6) << 14) + (((kA & 63) << 1) ^ aX);
                const uint32_t kB  = (uint32_t)(c * 16 + kb);
                const uint32_t kxB = ((kB >> 6) << 14) + (((kB & 63) << 1) ^ bX);

                uint32_t ah0[4], ah1[4], bhf[8][2];
                LDSM_X4(ah0, actH + aP0 + kxA);
                LDSM_X4(ah1, actH + aP1 + kxA);
                #pragma unroll
                for (int nt = 0; nt < 8; nt++)
                    LDSM_X2(bhf[nt], bH + bRow + ((uint32_t)nt << 10) + kxB);
                #pragma unroll
                for (int nt = 0; nt < 8; nt++) {
                    MMA16816(acc[0][nt], ah0, bhf[nt]);
                    MMA16816(acc[1][nt], ah1, bhf[nt]);
                }
                uint32_t al0[4], al1[4];
                LDSM_X4(al0, actL + aP0 + kxA);
                LDSM_X4(al1, actL + aP1 + kxA);
                #pragma unroll
                for (int nt = 0; nt < 8; nt++) {
                    MMA16816(acc[0][nt], al0, bhf[nt]);
                    MMA16816(acc[1][nt], al1, bhf[nt]);
                }
                #pragma unroll
                for (int nt = 0; nt < 8; nt++) {
                    uint32_t blf[2];
                    LDSM_X2(blf, bL + bRow + ((uint32_t)nt << 10) + kxB);
                    MMA16816(acc[0][nt], ah0, blf);
                    MMA16816(acc[1][nt], ah1, blf);
                }
            }
            __syncthreads();   // everyone done reading act before epilogue rewrites it

            if (l < 2) {
                const float* bias = sbias + l * 128;
                const int q = lane >> 2;
                #pragma unroll
                for (int mt = 0; mt < 2; mt++) {
                    const uint32_t rp0 = (uint32_t)(((wm * 4 + mt * 2) << 10) | (q << 7));
                    const uint32_t rp1 = rp0 + (1u << 10);
                    #pragma unroll
                    for (int nt = 0; nt < 8; nt++) {
                        const int cc = wn * 64 + nt * 8 + (lane & 3) * 2;
                        const float b0v = bias[cc], b1v = bias[cc + 1];
                        float s0 = swishf(acc[mt][nt][0] + b0v);
                        float s1 = swishf(acc[mt][nt][1] + b1v);
                        float s2 = swishf(acc[mt][nt][2] + b0v);
                        float s3 = swishf(acc[mt][nt][3] + b1v);
                        __nv_bfloat162 h01 = __floats2bfloat162_rn(s0, s1);
                        __nv_bfloat162 h23 = __floats2bfloat162_rn(s2, s3);
                        float l0 = s0 - __bfloat162float(__low2bfloat16(h01));
                        float l1 = s1 - __bfloat162float(__high2bfloat16(h01));
                        float l2 = s2 - __bfloat162float(__low2bfloat16(h23));
                        float l3 = s3 - __bfloat162float(__high2bfloat16(h23));
                        __nv_bfloat162 g01 = __floats2bfloat162_rn(l0, l1);
                        __nv_bfloat162 g23 = __floats2bfloat162_rn(l2, l3);
                        const uint32_t kx = (uint32_t)(((cc >> 6) << 14) +
                                            ((((cc & 63)) << 1) ^ (q << 4)));
                        *reinterpret_cast<uint32_t*>(smc + SM_ACT_H + rp0 + kx) = *reinterpret_cast<uint32_t*>(&h01);
                        *reinterpret_cast<uint32_t*>(smc + SM_ACT_L + rp0 + kx) = *reinterpret_cast<uint32_t*>(&g01);
                        *reinterpret_cast<uint32_t*>(smc + SM_ACT_H + rp1 + kx) = *reinterpret_cast<uint32_t*>(&h23);
                        *reinterpret_cast<uint32_t*>(smc + SM_ACT_L + rp1 + kx) = *reinterpret_cast<uint32_t*>(&g23);
                    }
                }
                __syncthreads();
            } else {
                // fused scalar head
                float ps[4] = {0.f, 0.f, 0.f, 0.f};
                #pragma unroll
                for (int mt = 0; mt < 2; mt++) {
                    #pragma unroll
                    for (int nt = 0; nt < 8; nt++) {
                        const int cc = wn * 64 + nt * 8 + (lane & 3) * 2;
                        const float b0v = sbias[256 + cc], b1v = sbias[256 + cc + 1];
                        const float w0 = sWo[cc], w1 = sWo[cc + 1];
                        ps[mt * 2 + 0] += swishf(acc[mt][nt][0] + b0v) * w0
                                        + swishf(acc[mt][nt][1] + b1v) * w1;
                        ps[mt * 2 + 1] += swishf(acc[mt][nt][2] + b0v) * w0
                                        + swishf(acc[mt][nt][3] + b1v) * w1;
                    }
                }
                #pragma unroll
                for (int i = 0; i < 4; i++) {
                    ps[i] += __shfl_xor_sync(0xffffffffu, ps[i], 1);
                    ps[i] += __shfl_xor_sync(0xffffffffu, ps[i], 2);
                }
                if ((lane & 3) == 0) {
                    const int rbase = wm * 32 + (lane >> 2);
                    atomicAdd(&sPart[rbase],      ps[0]);
                    atomicAdd(&sPart[rbase + 8],  ps[1]);
                    atomicAdd(&sPart[rbase + 16], ps[2]);
                    atomicAdd(&sPart[rbase + 24], ps[3]);
                }
                __syncthreads();
            }
        }

        if (tid < 128) out[(size_t)(m0 + tid) * 32 + o] = sPart[tid] + bo_v;
        __syncthreads();
    }
}

extern "C" void kernel_launch(void* const* d_in, const int* in_sizes, int n_in,
                              void* d_out, int out_size) {
    const float* x  = (const float*)d_in[0];
    const float* W1 = (const float*)d_in[1];
    const float* b1 = (const float*)d_in[2];
    const float* Wh = (const float*)d_in[3];
    const float* bh = (const float*)d_in[4];
    const float* Wo = (const float*)d_in[5];
    const float* bo = (const float*)d_in[6];
    float* out = (float*)d_out;

    cudaFuncSetAttribute(mlp_fused_kernel,
                         cudaFuncAttributeMaxDynamicSharedMemorySize, SM_TOTAL);
    mlp_fused_kernel<<<GROUPS * 32, THREADS, SM_TOTAL>>>(x, W1, b1, Wh, bh, Wo, bo, out);
}

// round 3
// speedup vs baseline: 1.7058x; 1.7058x over previous
#include <cuda_runtime.h>
#include <cuda_fp16.h>
#include <cstdint>

// ============================================================
// SparseModel: 32 MLPs (64 -> 128 -> 128 -> 128 -> 1, swish)
// HMMA fp16 kernel: act split hi/lo fp16 (2-pass), weights fp16 (1 rounding).
// 4 independent 2-warp pipelines per CTA via named barriers.
// ============================================================

#define THREADS 256
#define TILE_M 128
#define GROUPS 32
#define TILES_PER_CTA 8

// ---- smem layout ----
static constexpr int SM_ACT_H = 0;        // act hi [128 x 128 fp16] swizzled
static constexpr int SM_ACT_L = 32768;    // act lo
static constexpr int SM_W1    = 65536;    // W1  [128n x 64k fp16]
static constexpr int SM_WH0   = 81920;    // Wh0 [128n x 128k fp16]
static constexpr int SM_WH1   = 114688;
static constexpr int SM_PART  = 147456;          // 256 floats (pair-disjoint head partials)
static constexpr int SM_BIAS  = SM_PART + 1024;  // 3 x 128 floats
static constexpr int SM_WO    = SM_BIAS + 1536;  // 128 floats
static constexpr int SM_TOTAL = SM_WO + 512;     // 150528

// ---- helpers ----
__device__ __forceinline__ uint32_t smem_to_u32(const void* p) {
    uint32_t a;
    asm("{ .reg .u64 t; cvta.to.shared.u64 t, %1; cvt.u32.u64 %0, t; }" : "=r"(a) : "l"(p));
    return a;
}
__device__ __forceinline__ uint32_t swz(uint32_t b) { return b ^ ((b >> 3) & 0x70u); }
__device__ __forceinline__ uint32_t toff(int r, int k) {
    return (uint32_t)(((((k >> 6) << 4) + (r >> 3)) << 10) | ((r & 7) << 7) | ((k & 63) << 1));
}

#define LDSM_X4(r, addr) \
    asm volatile("ldmatrix.sync.aligned.m8n8.x4.shared.b16 {%0,%1,%2,%3}, [%4];" \
        : "=r"((r)[0]), "=r"((r)[1]), "=r"((r)[2]), "=r"((r)[3]) : "r"(addr))
#define MMA16816(d, a, b) \
    asm volatile("mma.sync.aligned.m16n8k16.row.col.f32.f16.f16.f32 " \
        "{%0,%1,%2,%3}, {%4,%5,%6,%7}, {%8,%9}, {%0,%1,%2,%3};" \
        : "+f"((d)[0]), "+f"((d)[1]), "+f"((d)[2]), "+f"((d)[3]) \
        : "r"((a)[0]), "r"((a)[1]), "r"((a)[2]), "r"((a)[3]), "r"((b)[0]), "r"((b)[1]))
#define BARP(id) asm volatile("bar.sync %0, 64;" :: "r"(id) : "memory")

__device__ __forceinline__ float swishf(float v) {
    return __fdividef(v, 1.0f + __expf(-v));
}

__global__ void __launch_bounds__(THREADS, 1)
mlp_fused_kernel(const float* __restrict__ x,  const float* __restrict__ W1,
                 const float* __restrict__ b1, const float* __restrict__ Wh,
                 const float* __restrict__ bh, const float* __restrict__ Wo,
                 const float* __restrict__ bo, float* __restrict__ out)
{
    extern __shared__ char smc[];
    const uint32_t smb = smem_to_u32(smc);
    const int tid = threadIdx.x;
    const int wid = tid >> 5;
    const int lane = tid & 31;
    const int o = blockIdx.x & 31;       // subnet
    const int g = blockIdx.x >> 5;       // row group

    // pair decomposition: pair index wm = wid>>1 (rows), wn = wid&1 (col half)
    const int wm = wid >> 1;
    const int wn = wid & 1;
    const int barid = 1 + wm;

    // ---- stage weights (fp16, single rounding) ----
    {
        const float* W1p = W1 + o * 64 * 128;
        for (int idx = tid; idx < 64 * 128; idx += THREADS) {
            int k = idx >> 7, j = idx & 127;         // W1[o][k][j] -> B[n=j][k]
            *reinterpret_cast<__half*>(smc + SM_W1 + swz(toff(j, k))) = __float2half_rn(W1p[idx]);
        }
        #pragma unroll
        for (int l = 0; l < 2; l++) {
            const float* Wp = Wh + ((size_t)l * 32 + o) * 128 * 128;
            const int base = l ? SM_WH1 : SM_WH0;
            for (int idx = tid; idx < 128 * 128; idx += THREADS) {
                int k = idx >> 7, j = idx & 127;
                *reinterpret_cast<__half*>(smc + base + swz(toff(j, k))) = __float2half_rn(Wp[idx]);
            }
        }
        for (int j = tid; j < 128; j += THREADS) {
            reinterpret_cast<float*>(smc + SM_BIAS)[j]       = b1[o * 128 + j];
            reinterpret_cast<float*>(smc + SM_BIAS)[128 + j] = bh[(size_t)o * 128 + j];
            reinterpret_cast<float*>(smc + SM_BIAS)[256 + j] = bh[((size_t)32 + o) * 128 + j];
            reinterpret_cast<float*>(smc + SM_WO)[j]         = Wo[o * 128 + j];
        }
    }
    __syncthreads();

    const float bo_v   = bo[o];
    const float* sbias = reinterpret_cast<const float*>(smc + SM_BIAS);
    const float* sWo   = reinterpret_cast<const float*>(smc + SM_WO);
    float* sPart       = reinterpret_cast<float*>(smc + SM_PART);

    // ---- ldmatrix lane addressing ----
    // A frags (16x16): lanes 0-7 r+0/k+0, 8-15 r+8/k+0, 16-23 r+0/k+8, 24-31 r+8/k+8
    const int ra0 = wm * 32 + ((lane >> 3) & 1) * 8 + (lane & 7);
    const uint32_t aP0 = (uint32_t)(((ra0 >> 3) << 10) | ((ra0 & 7) << 7));
    const uint32_t aP1 = aP0 + (2u << 10);             // +16 rows
    const uint32_t aX  = (uint32_t)((lane & 7) << 4);
    const int ka = (lane >> 4) * 8;
    // B x4 frags: quad 0: n+0..7/k+0, 1: n+0..7/k+8, 2: n+8..15/k+0, 3: n+8..15/k+8
    const int quad = lane >> 3;
    const int nb   = ((quad >> 1) << 3) + (lane & 7);
    const int kb4  = (quad & 1) << 3;
    const uint32_t bRow0 = (uint32_t)(((wn * 8 + (nb >> 3)) << 10) | ((nb & 7) << 7));
    const uint32_t bX    = (uint32_t)((lane & 7) << 4);

    const uint32_t actH = smb + SM_ACT_H, actL = smb + SM_ACT_L;
    const uint32_t wBase[3] = { smb + SM_W1, smb + SM_WH0, smb + SM_WH1 };

    for (int t = 0; t < TILES_PER_CTA; t++) {
        const int m0 = (g * TILES_PER_CTA + t) * TILE_M;

        // ---- stage X rows for this pair: [32 rows x 64 k] fp32 -> fp16 hi/lo ----
        {
            const int p = wn * 32 + lane;           // 0..63 within pair
            const int r = wm * 32 + (p >> 1);
            const int kbx = (p & 1) << 5;
            const float4* xp = reinterpret_cast<const float4*>(x + (size_t)(m0 + r) * 64 + kbx);
            #pragma unroll
            for (int q = 0; q < 8; q++) {
                float4 v = xp[q];
                __half h0 = __float2half_rn(v.x), h1 = __float2half_rn(v.y);
                __half h2 = __float2half_rn(v.z), h3 = __float2half_rn(v.w);
                __half2 hh01 = __halves2half2(h0, h1), hh23 = __halves2half2(h2, h3);
                __half2 ll01 = __halves2half2(__float2half_rn(v.x - __half2float(h0)),
                                              __float2half_rn(v.y - __half2float(h1)));
                __half2 ll23 = __halves2half2(__float2half_rn(v.z - __half2float(h2)),
                                              __float2half_rn(v.w - __half2float(h3)));
                uint32_t off0 = swz(toff(r, kbx + 4 * q));
                uint32_t off1 = swz(toff(r, kbx + 4 * q + 2));
                *reinterpret_cast<uint32_t*>(smc + SM_ACT_H + off0) = *reinterpret_cast<uint32_t*>(&hh01);
                *reinterpret_cast<uint32_t*>(smc + SM_ACT_H + off1) = *reinterpret_cast<uint32_t*>(&hh23);
                *reinterpret_cast<uint32_t*>(smc + SM_ACT_L + off0) = *reinterpret_cast<uint32_t*>(&ll01);
                *reinterpret_cast<uint32_t*>(smc + SM_ACT_L + off1) = *reinterpret_cast<uint32_t*>(&ll23);
            }
        }
        BARP(barid);

        // ---- 3 layers ----
        for (int l = 0; l < 3; l++) {
            const int nch = (l == 0) ? 4 : 8;
            const uint32_t wB = wBase[l];

            float acc[2][8][4];
            #pragma unroll
            for (int mt = 0; mt < 2; mt++)
                #pragma unroll
                for (int nt = 0; nt < 8; nt++)
                    #pragma unroll
                    for (int e = 0; e < 4; e++) acc[mt][nt][e] = 0.0f;

            for (int c = 0; c < nch; ++c) {
                const uint32_t kA  = (uint32_t)(c * 16 + ka);
                const uint32_t kxA = ((kA >> 6) << 14) + (((kA & 63) << 1) ^ aX);
                const uint32_t kB  = (uint32_t)(c * 16 + kb4);
                const uint32_t kxB = ((kB >> 6) << 14) + (((kB & 63) << 1) ^ bX);

                uint32_t ah0[4], ah1[4], al0[4], al1[4], bf[8][2];
                LDSM_X4(ah0, actH + aP0 + kxA);
                LDSM_X4(ah1, actH + aP1 + kxA);
                LDSM_X4(al0, actL + aP0 + kxA);
                LDSM_X4(al1, actL + aP1 + kxA);
                #pragma unroll
                for (int np = 0; np < 4; np++) {
                    uint32_t q4[4];
                    LDSM_X4(q4, wB + bRow0 + ((uint32_t)np << 11) + kxB);
                    bf[2*np][0]   = q4[0]; bf[2*np][1]   = q4[1];
                    bf[2*np+1][0] = q4[2]; bf[2*np+1][1] = q4[3];
                }
                #pragma unroll
                for (int nt = 0; nt < 8; nt++) {
                    MMA16816(acc[0][nt], ah0, bf[nt]);
                    MMA16816(acc[1][nt], ah1, bf[nt]);
                }
                #pragma unroll
                for (int nt = 0; nt < 8; nt++) {
                    MMA16816(acc[0][nt], al0, bf[nt]);
                    MMA16816(acc[1][nt], al1, bf[nt]);
                }
            }

            if (l < 2) {
                BARP(barid);   // pair done reading act before rewriting it
                const float* bias = sbias + l * 128;
                const int q = lane >> 2;
                #pragma unroll
                for (int mt = 0; mt < 2; mt++) {
                    const uint32_t rp0 = (uint32_t)(((wm * 4 + mt * 2) << 10) | (q << 7));
                    const uint32_t rp1 = rp0 + (1u << 10);
                    #pragma unroll
                    for (int nt = 0; nt < 8; nt++) {
                        const int cc = wn * 64 + nt * 8 + (lane & 3) * 2;
                        const float b0v = bias[cc], b1v = bias[cc + 1];
                        float s0 = swishf(acc[mt][nt][0] + b0v);
                        float s1 = swishf(acc[mt][nt][1] + b1v);
                        float s2 = swishf(acc[mt][nt][2] + b0v);
                        float s3 = swishf(acc[mt][nt][3] + b1v);
                        __half h0 = __float2half_rn(s0), h1 = __float2half_rn(s1);
                        __half h2 = __float2half_rn(s2), h3 = __float2half_rn(s3);
                        __half2 hh01 = __halves2half2(h0, h1), hh23 = __halves2half2(h2, h3);
                        __half2 ll01 = __halves2half2(__float2half_rn(s0 - __half2float(h0)),
                                                      __float2half_rn(s1 - __half2float(h1)));
                        __half2 ll23 = __halves2half2(__float2half_rn(s2 - __half2float(h2)),
                                                      __float2half_rn(s3 - __half2float(h3)));
                        const uint32_t kx = (uint32_t)(((cc >> 6) << 14) +
                                            (((cc & 63) << 1) ^ (q << 4)));
                        *reinterpret_cast<uint32_t*>(smc + SM_ACT_H + rp0 + kx) = *reinterpret_cast<uint32_t*>(&hh01);
                        *reinterpret_cast<uint32_t*>(smc + SM_ACT_L + rp0 + kx) = *reinterpret_cast<uint32_t*>(&ll01);
                        *reinterpret_cast<uint32_t*>(smc + SM_ACT_H + rp1 + kx) = *reinterpret_cast<uint32_t*>(&hh23);
                        *reinterpret_cast<uint32_t*>(smc + SM_ACT_L + rp1 + kx) = *reinterpret_cast<uint32_t*>(&ll23);
                    }
                }
                BARP(barid);   // writes visible before next layer's reads
            } else {
                // fused scalar head (no act writes, no atomics)
                float ps[4] = {0.f, 0.f, 0.f, 0.f};
                #pragma unroll
                for (int mt = 0; mt < 2; mt++) {
                    #pragma unroll
                    for (int nt = 0; nt < 8; nt++) {
                        const int cc = wn * 64 + nt * 8 + (lane & 3) * 2;
                        const float b0v = sbias[256 + cc], b1v = sbias[256 + cc + 1];
                        const float w0 = sWo[cc], w1 = sWo[cc + 1];
                        ps[mt * 2 + 0] += swishf(acc[mt][nt][0] + b0v) * w0
                                        + swishf(acc[mt][nt][1] + b1v) * w1;
                        ps[mt * 2 + 1] += swishf(acc[mt][nt][2] + b0v) * w0
                                        + swishf(acc[mt][nt][3] + b1v) * w1;
                    }
                }
                #pragma unroll
                for (int i = 0; i < 4; i++) {
                    ps[i] += __shfl_xor_sync(0xffffffffu, ps[i], 1);
                    ps[i] += __shfl_xor_sync(0xffffffffu, ps[i], 2);
                }
                if ((lane & 3) == 0) {
                    const int rl = lane >> 2;     // 0..7
                    float* sp = sPart + wm * 64 + wn * 32;
                    sp[rl]      = ps[0];
                    sp[rl + 8]  = ps[1];
                    sp[rl + 16] = ps[2];
                    sp[rl + 24] = ps[3];
                }
                BARP(barid);
                if (wn == 0) {
                    float v = sPart[wm * 64 + lane] + sPart[wm * 64 + 32 + lane];
                    out[(size_t)(m0 + wm * 32 + lane) * 32 + o] = v + bo_v;
                }
            }
        }
    }
}

extern "C" void kernel_launch(void* const* d_in, const int* in_sizes, int n_in,
                              void* d_out, int out_size) {
    const float* x  = (const float*)d_in[0];
    const float* W1 = (const float*)d_in[1];
    const float* b1 = (const float*)d_in[2];
    const float* Wh = (const float*)d_in[3];
    const float* bh = (const float*)d_in[4];
    const float* Wo = (const float*)d_in[5];
    const float* bo = (const float*)d_in[6];
    float* out = (float*)d_out;

    cudaFuncSetAttribute(mlp_fused_kernel,
                         cudaFuncAttributeMaxDynamicSharedMemorySize, SM_TOTAL);
    mlp_fused_kernel<<<GROUPS * 32, THREADS, SM_TOTAL>>>(x, W1, b1, Wh, bh, Wo, bo, out);
}

// round 4
// speedup vs baseline: 1.8642x; 1.0929x over previous
#include <cuda_runtime.h>
#include <cuda_fp16.h>
#include <cstdint>

// ============================================================
// SparseModel: 32 MLPs (64 -> 128 -> 128 -> 128 -> 1, swish)
// HMMA fp16: act split hi/lo (2-pass), weights fp16 (1 rounding).
// 512 threads / 16 warps: 8 independent 2-warp row-pair pipelines.
// ============================================================

#define THREADS 512
#define TILE_M 128
#define GROUPS 32
#define TILES_PER_CTA 8

// ---- smem layout ----
static constexpr int SM_ACT_H = 0;        // act hi [128 x 128 fp16] swizzled
static constexpr int SM_ACT_L = 32768;    // act lo
static constexpr int SM_W1    = 65536;    // W1  [128n x 64k fp16]
static constexpr int SM_WH0   = 81920;    // Wh0 [128n x 128k fp16]
static constexpr int SM_WH1   = 114688;
static constexpr int SM_PART  = 147456;          // 256 floats (pair-disjoint)
static constexpr int SM_BIAS  = SM_PART + 1024;  // 3 x 128 floats
static constexpr int SM_WO    = SM_BIAS + 1536;  // 128 floats
static constexpr int SM_TOTAL = SM_WO + 512;     // 150528

// ---- helpers ----
__device__ __forceinline__ uint32_t smem_to_u32(const void* p) {
    uint32_t a;
    asm("{ .reg .u64 t; cvta.to.shared.u64 t, %1; cvt.u32.u64 %0, t; }" : "=r"(a) : "l"(p));
    return a;
}
__device__ __forceinline__ uint32_t swz(uint32_t b) { return b ^ ((b >> 3) & 0x70u); }
__device__ __forceinline__ uint32_t toff(int r, int k) {
    return (uint32_t)(((((k >> 6) << 4) + (r >> 3)) << 10) | ((r & 7) << 7) | ((k & 63) << 1));
}

#define LDSM_X4(r, addr) \
    asm volatile("ldmatrix.sync.aligned.m8n8.x4.shared.b16 {%0,%1,%2,%3}, [%4];" \
        : "=r"((r)[0]), "=r"((r)[1]), "=r"((r)[2]), "=r"((r)[3]) : "r"(addr))
#define MMA16816(d, a, b) \
    asm volatile("mma.sync.aligned.m16n8k16.row.col.f32.f16.f16.f32 " \
        "{%0,%1,%2,%3}, {%4,%5,%6,%7}, {%8,%9}, {%0,%1,%2,%3};" \
        : "+f"((d)[0]), "+f"((d)[1]), "+f"((d)[2]), "+f"((d)[3]) \
        : "r"((a)[0]), "r"((a)[1]), "r"((a)[2]), "r"((a)[3]), "r"((b)[0]), "r"((b)[1]))
#define BARP(id) asm volatile("bar.sync %0, 64;" :: "r"(id) : "memory")

__device__ __forceinline__ float swishf(float v) {
    return __fdividef(v, 1.0f + __expf(-v));
}

__global__ void __launch_bounds__(THREADS, 1)
mlp_fused_kernel(const float* __restrict__ x,  const float* __restrict__ W1,
                 const float* __restrict__ b1, const float* __restrict__ Wh,
                 const float* __restrict__ bh, const float* __restrict__ Wo,
                 const float* __restrict__ bo, float* __restrict__ out)
{
    extern __shared__ char smc[];
    const uint32_t smb = smem_to_u32(smc);
    const int tid = threadIdx.x;
    const int wid = tid >> 5;
    const int lane = tid & 31;
    const int o = blockIdx.x & 31;       // subnet
    const int g = blockIdx.x >> 5;       // row group

    // pair decomposition: pm = row pair (16 rows), wn = column half (64 cols)
    const int pm = wid >> 1;             // 0..7
    const int wn = wid & 1;
    const int barid = 1 + pm;            // named barriers 1..8

    // ---- stage weights (fp16, single rounding) ----
    {
        const float* W1p = W1 + o * 64 * 128;
        for (int idx = tid; idx < 64 * 128; idx += THREADS) {
            int k = idx >> 7, j = idx & 127;         // W1[o][k][j] -> B[n=j][k]
            *reinterpret_cast<__half*>(smc + SM_W1 + swz(toff(j, k))) = __float2half_rn(W1p[idx]);
        }
        #pragma unroll
        for (int l = 0; l < 2; l++) {
            const float* Wp = Wh + ((size_t)l * 32 + o) * 128 * 128;
            const int base = l ? SM_WH1 : SM_WH0;
            for (int idx = tid; idx < 128 * 128; idx += THREADS) {
                int k = idx >> 7, j = idx & 127;
                *reinterpret_cast<__half*>(smc + base + swz(toff(j, k))) = __float2half_rn(Wp[idx]);
            }
        }
        for (int j = tid; j < 128; j += THREADS) {
            reinterpret_cast<float*>(smc + SM_BIAS)[j]       = b1[o * 128 + j];
            reinterpret_cast<float*>(smc + SM_BIAS)[128 + j] = bh[(size_t)o * 128 + j];
            reinterpret_cast<float*>(smc + SM_BIAS)[256 + j] = bh[((size_t)32 + o) * 128 + j];
            reinterpret_cast<float*>(smc + SM_WO)[j]         = Wo[o * 128 + j];
        }
    }
    __syncthreads();

    const float bo_v   = bo[o];
    const float* sbias = reinterpret_cast<const float*>(smc + SM_BIAS);
    const float* sWo   = reinterpret_cast<const float*>(smc + SM_WO);
    float* sPart       = reinterpret_cast<float*>(smc + SM_PART);

    // ---- ldmatrix lane addressing ----
    // A frag (16x16): lanes 0-7 r+0/k+0, 8-15 r+8/k+0, 16-23 r+0/k+8, 24-31 r+8/k+8
    const int ra0 = pm * 16 + ((lane >> 3) & 1) * 8 + (lane & 7);
    const uint32_t aP0 = (uint32_t)(((ra0 >> 3) << 10) | ((ra0 & 7) << 7));
    const uint32_t aX  = (uint32_t)((lane & 7) << 4);
    const int ka = (lane >> 4) * 8;
    // B x4 frags: quad 0: n+0..7/k+0, 1: n+0..7/k+8, 2: n+8..15/k+0, 3: n+8..15/k+8
    const int quad = lane >> 3;
    const int nb   = ((quad >> 1) << 3) + (lane & 7);
    const int kb4  = (quad & 1) << 3;
    const uint32_t bRow0 = (uint32_t)(((wn * 8 + (nb >> 3)) << 10) | ((nb & 7) << 7));
    const uint32_t bX    = (uint32_t)((lane & 7) << 4);

    const uint32_t actH = smb + SM_ACT_H, actL = smb + SM_ACT_L;
    const uint32_t wBase[3] = { smb + SM_W1, smb + SM_WH0, smb + SM_WH1 };

    for (int t = 0; t < TILES_PER_CTA; t++) {
        const int m0 = (g * TILES_PER_CTA + t) * TILE_M;

        // ---- stage X rows for this pair: [16 rows x 64 k] fp32 -> fp16 hi/lo ----
        {
            const int p = wn * 32 + lane;             // 0..63 within pair
            const int r = pm * 16 + (p >> 2);         // row (16 per pair)
            const int kbx = (p & 3) << 4;             // k base (4 x 16)
            const float4* xp = reinterpret_cast<const float4*>(x + (size_t)(m0 + r) * 64 + kbx);
            #pragma unroll
            for (int q = 0; q < 4; q++) {
                float4 v = xp[q];
                __half h0 = __float2half_rn(v.x), h1 = __float2half_rn(v.y);
                __half h2 = __float2half_rn(v.z), h3 = __float2half_rn(v.w);
                __half2 hh01 = __halves2half2(h0, h1), hh23 = __halves2half2(h2, h3);
                __half2 ll01 = __halves2half2(__float2half_rn(v.x - __half2float(h0)),
                                              __float2half_rn(v.y - __half2float(h1)));
                __half2 ll23 = __halves2half2(__float2half_rn(v.z - __half2float(h2)),
                                              __float2half_rn(v.w - __half2float(h3)));
                uint32_t off0 = swz(toff(r, kbx + 4 * q));
                uint32_t off1 = swz(toff(r, kbx + 4 * q + 2));
                *reinterpret_cast<uint32_t*>(smc + SM_ACT_H + off0) = *reinterpret_cast<uint32_t*>(&hh01);
                *reinterpret_cast<uint32_t*>(smc + SM_ACT_H + off1) = *reinterpret_cast<uint32_t*>(&hh23);
                *reinterpret_cast<uint32_t*>(smc + SM_ACT_L + off0) = *reinterpret_cast<uint32_t*>(&ll01);
                *reinterpret_cast<uint32_t*>(smc + SM_ACT_L + off1) = *reinterpret_cast<uint32_t*>(&ll23);
            }
        }
        BARP(barid);

        // ---- 3 layers ----
        for (int l = 0; l < 3; l++) {
            const int nch = (l == 0) ? 4 : 8;
            const uint32_t wB = wBase[l];

            float acc[8][4];
            #pragma unroll
            for (int nt = 0; nt < 8; nt++)
                #pragma unroll
                for (int e = 0; e < 4; e++) acc[nt][e] = 0.0f;

            for (int c = 0; c < nch; ++c) {
                const uint32_t kA  = (uint32_t)(c * 16 + ka);
                const uint32_t kxA = ((kA >> 6) << 14) + (((kA & 63) << 1) ^ aX);
                const uint32_t kB  = (uint32_t)(c * 16 + kb4);
                const uint32_t kxB = ((kB >> 6) << 14) + (((kB & 63) << 1) ^ bX);

                uint32_t ah[4], al[4], bf[8][2];
                LDSM_X4(ah, actH + aP0 + kxA);
                LDSM_X4(al, actL + aP0 + kxA);
                #pragma unroll
                for (int np = 0; np < 4; np++) {
                    uint32_t q4[4];
                    LDSM_X4(q4, wB + bRow0 + ((uint32_t)np << 11) + kxB);
                    bf[2*np][0]   = q4[0]; bf[2*np][1]   = q4[1];
                    bf[2*np+1][0] = q4[2]; bf[2*np+1][1] = q4[3];
                }
                #pragma unroll
                for (int nt = 0; nt < 8; nt++)
                    MMA16816(acc[nt], ah, bf[nt]);
                #pragma unroll
                for (int nt = 0; nt < 8; nt++)
                    MMA16816(acc[nt], al, bf[nt]);
            }

            if (l < 2) {
                BARP(barid);   // pair done reading act before rewriting it
                const float* bias = sbias + l * 128;
                const int q = lane >> 2;     // row within 8-row block
                const uint32_t rp0 = (uint32_t)(((pm * 2) << 10) | (q << 7));
                const uint32_t rp1 = rp0 + (1u << 10);
                #pragma unroll
                for (int nt = 0; nt < 8; nt++) {
                    const int cc = wn * 64 + nt * 8 + (lane & 3) * 2;
                    const float b0v = bias[cc], b1v = bias[cc + 1];
                    float s0 = swishf(acc[nt][0] + b0v);
                    float s1 = swishf(acc[nt][1] + b1v);
                    float s2 = swishf(acc[nt][2] + b0v);
                    float s3 = swishf(acc[nt][3] + b1v);
                    __half h0 = __float2half_rn(s0), h1 = __float2half_rn(s1);
                    __half h2 = __float2half_rn(s2), h3 = __float2half_rn(s3);
                    __half2 hh01 = __halves2half2(h0, h1), hh23 = __halves2half2(h2, h3);
                    __half2 ll01 = __halves2half2(__float2half_rn(s0 - __half2float(h0)),
                                                  __float2half_rn(s1 - __half2float(h1)));
                    __half2 ll23 = __halves2half2(__float2half_rn(s2 - __half2float(h2)),
                                                  __float2half_rn(s3 - __half2float(h3)));
                    const uint32_t kx = (uint32_t)(((cc >> 6) << 14) +
                                        (((cc & 63) << 1) ^ (q << 4)));
                    *reinterpret_cast<uint32_t*>(smc + SM_ACT_H + rp0 + kx) = *reinterpret_cast<uint32_t*>(&hh01);
                    *reinterpret_cast<uint32_t*>(smc + SM_ACT_L + rp0 + kx) = *reinterpret_cast<uint32_t*>(&ll01);
                    *reinterpret_cast<uint32_t*>(smc + SM_ACT_H + rp1 + kx) = *reinterpret_cast<uint32_t*>(&hh23);
                    *reinterpret_cast<uint32_t*>(smc + SM_ACT_L + rp1 + kx) = *reinterpret_cast<uint32_t*>(&ll23);
                }
                BARP(barid);   // writes visible before next layer's reads
            } else {
                // fused scalar head
                float ps0 = 0.f, ps1 = 0.f;
                #pragma unroll
                for (int nt = 0; nt < 8; nt++) {
                    const int cc = wn * 64 + nt * 8 + (lane & 3) * 2;
                    const float b0v = sbias[256 + cc], b1v = sbias[256 + cc + 1];
                    const float w0 = sWo[cc], w1 = sWo[cc + 1];
                    ps0 += swishf(acc[nt][0] + b0v) * w0 + swishf(acc[nt][1] + b1v) * w1;
                    ps1 += swishf(acc[nt][2] + b0v) * w0 + swishf(acc[nt][3] + b1v) * w1;
                }
                ps0 += __shfl_xor_sync(0xffffffffu, ps0, 1);
                ps0 += __shfl_xor_sync(0xffffffffu, ps0, 2);
                ps1 += __shfl_xor_sync(0xffffffffu, ps1, 1);
                ps1 += __shfl_xor_sync(0xffffffffu, ps1, 2);
                if ((lane & 3) == 0) {
                    const int r = lane >> 2;             // 0..7
                    float* sp = sPart + pm * 32 + wn * 16;
                    sp[r]     = ps0;
                    sp[r + 8] = ps1;
                }
                BARP(barid);
                if (wn == 0 && lane < 16) {
                    float v = sPart[pm * 32 + lane] + sPart[pm * 32 + 16 + lane];
                    out[(size_t)(m0 + pm * 16 + lane) * 32 + o] = v + bo_v;
                }
            }
        }
    }
}

extern "C" void kernel_launch(void* const* d_in, const int* in_sizes, int n_in,
                              void* d_out, int out_size) {
    const float* x  = (const float*)d_in[0];
    const float* W1 = (const float*)d_in[1];
    const float* b1 = (const float*)d_in[2];
    const float* Wh = (const float*)d_in[3];
    const float* bh = (const float*)d_in[4];
    const float* Wo = (const float*)d_in[5];
    const float* bo = (const float*)d_in[6];
    float* out = (float*)d_out;

    cudaFuncSetAttribute(mlp_fused_kernel,
                         cudaFuncAttributeMaxDynamicSharedMemorySize, SM_TOTAL);
    mlp_fused_kernel<<<GROUPS * 32, THREADS, SM_TOTAL>>>(x, W1, b1, Wh, bh, Wo, bo, out);
}

// round 5
// speedup vs baseline: 2.4766x; 1.3285x over previous
#include <cuda_runtime.h>
#include <cuda_fp16.h>
#include <cstdint>

// ============================================================
// SparseModel: 32 MLPs (64 -> 128 -> 128 -> 128 -> 1, swish)
// HMMA fp16 single-pass (act fp16, weights fp16), warp tile 32x32,
// 16 warps = 4 row-groups x 4 column-quarters; per-group named barriers.
// ============================================================

#define THREADS 512
#define TILE_M 128
#define GROUPS 32
#define TILES_PER_CTA 8

// ---- smem layout ----
static constexpr int SM_ACT   = 0;        // act [128 x 128 fp16] swizzled
static constexpr int SM_W1    = 32768;    // W1  [128n x 64k fp16]
static constexpr int SM_WH0   = 49152;    // Wh0 [128n x 128k fp16]
static constexpr int SM_WH1   = 81920;
static constexpr int SM_PART  = 114688;          // 512 floats
static constexpr int SM_BIAS  = SM_PART + 2048;  // 3 x 128 floats
static constexpr int SM_WO    = SM_BIAS + 1536;  // 128 floats
static constexpr int SM_TOTAL = SM_WO + 512;     // 118784

// ---- helpers ----
__device__ __forceinline__ uint32_t smem_to_u32(const void* p) {
    uint32_t a;
    asm("{ .reg .u64 t; cvta.to.shared.u64 t, %1; cvt.u32.u64 %0, t; }" : "=r"(a) : "l"(p));
    return a;
}
__device__ __forceinline__ uint32_t swz(uint32_t b) { return b ^ ((b >> 3) & 0x70u); }
__device__ __forceinline__ uint32_t toff(int r, int k) {
    return (uint32_t)(((((k >> 6) << 4) + (r >> 3)) << 10) | ((r & 7) << 7) | ((k & 63) << 1));
}

#define LDSM_X4(r, addr) \
    asm volatile("ldmatrix.sync.aligned.m8n8.x4.shared.b16 {%0,%1,%2,%3}, [%4];" \
        : "=r"((r)[0]), "=r"((r)[1]), "=r"((r)[2]), "=r"((r)[3]) : "r"(addr))
#define MMA16816(d, a, b) \
    asm volatile("mma.sync.aligned.m16n8k16.row.col.f32.f16.f16.f32 " \
        "{%0,%1,%2,%3}, {%4,%5,%6,%7}, {%8,%9}, {%0,%1,%2,%3};" \
        : "+f"((d)[0]), "+f"((d)[1]), "+f"((d)[2]), "+f"((d)[3]) \
        : "r"((a)[0]), "r"((a)[1]), "r"((a)[2]), "r"((a)[3]), "r"((b)[0]), "r"((b)[1]))
#define BARG(id) asm volatile("bar.sync %0, 128;" :: "r"(id) : "memory")

__device__ __forceinline__ float swishf(float v) {
    return __fdividef(v, 1.0f + __expf(-v));
}

// fully-unrolled layer mainloop; acc[mt][nt][e]
template <int NCH>
__device__ __forceinline__ void layer_mma(
    float acc[2][4][4], uint32_t actB, uint32_t wB,
    uint32_t aP0, uint32_t aP1, uint32_t aX, int ka,
    uint32_t bRow0, uint32_t bX, int kb4)
{
    #pragma unroll
    for (int c = 0; c < NCH; ++c) {
        const uint32_t kA  = (uint32_t)(c * 16 + ka);
        const uint32_t kxA = ((kA >> 6) << 14) + (((kA & 63) << 1) ^ aX);
        const uint32_t kB  = (uint32_t)(c * 16 + kb4);
        const uint32_t kxB = ((kB >> 6) << 14) + (((kB & 63) << 1) ^ bX);

        uint32_t a0[4], a1[4], bf[4][2];
        LDSM_X4(a0, actB + aP0 + kxA);
        LDSM_X4(a1, actB + aP1 + kxA);
        #pragma unroll
        for (int np = 0; np < 2; np++) {
            uint32_t q4[4];
            LDSM_X4(q4, wB + bRow0 + ((uint32_t)np << 11) + kxB);
            bf[2*np][0]   = q4[0]; bf[2*np][1]   = q4[1];
            bf[2*np+1][0] = q4[2]; bf[2*np+1][1] = q4[3];
        }
        #pragma unroll
        for (int nt = 0; nt < 4; nt++) {
            MMA16816(acc[0][nt], a0, bf[nt]);
            MMA16816(acc[1][nt], a1, bf[nt]);
        }
    }
}

__global__ void __launch_bounds__(THREADS, 1)
mlp_fused_kernel(const float* __restrict__ x,  const float* __restrict__ W1,
                 const float* __restrict__ b1, const float* __restrict__ Wh,
                 const float* __restrict__ bh, const float* __restrict__ Wo,
                 const float* __restrict__ bo, float* __restrict__ out)
{
    extern __shared__ char smc[];
    const uint32_t smb = smem_to_u32(smc);
    const int tid = threadIdx.x;
    const int wid = tid >> 5;
    const int lane = tid & 31;
    const int o = blockIdx.x & 31;       // subnet
    const int g = blockIdx.x >> 5;       // row group of 1024 rows

    // decomposition: rg = row group (32 rows), wq = column quarter (32 cols)
    const int rg = wid >> 2;             // 0..3
    const int wq = wid & 3;              // 0..3
    const int barid = 1 + rg;            // named barriers 1..4 (128 threads each)

    // ---- stage weights (fp16, single rounding) ----
    {
        const float* W1p = W1 + o * 64 * 128;
        for (int idx = tid; idx < 64 * 128; idx += THREADS) {
            int k = idx >> 7, j = idx & 127;         // W1[o][k][j] -> B[n=j][k]
            *reinterpret_cast<__half*>(smc + SM_W1 + swz(toff(j, k))) = __float2half_rn(W1p[idx]);
        }
        #pragma unroll
        for (int l = 0; l < 2; l++) {
            const float* Wp = Wh + ((size_t)l * 32 + o) * 128 * 128;
            const int base = l ? SM_WH1 : SM_WH0;
            for (int idx = tid; idx < 128 * 128; idx += THREADS) {
                int k = idx >> 7, j = idx & 127;
                *reinterpret_cast<__half*>(smc + base + swz(toff(j, k))) = __float2half_rn(Wp[idx]);
            }
        }
        for (int j = tid; j < 128; j += THREADS) {
            reinterpret_cast<float*>(smc + SM_BIAS)[j]       = b1[o * 128 + j];
            reinterpret_cast<float*>(smc + SM_BIAS)[128 + j] = bh[(size_t)o * 128 + j];
            reinterpret_cast<float*>(smc + SM_BIAS)[256 + j] = bh[((size_t)32 + o) * 128 + j];
            reinterpret_cast<float*>(smc + SM_WO)[j]         = Wo[o * 128 + j];
        }
    }
    __syncthreads();

    const float bo_v   = bo[o];
    const float* sbias = reinterpret_cast<const float*>(smc + SM_BIAS);
    const float* sWo   = reinterpret_cast<const float*>(smc + SM_WO);
    float* sPart       = reinterpret_cast<float*>(smc + SM_PART);

    // ---- ldmatrix lane addressing ----
    // A frag (16x16): lanes 0-7 r+0/k+0, 8-15 r+8/k+0, 16-23 r+0/k+8, 24-31 r+8/k+8
    const int ra0 = rg * 32 + ((lane >> 3) & 1) * 8 + (lane & 7);
    const uint32_t aP0 = (uint32_t)(((ra0 >> 3) << 10) | ((ra0 & 7) << 7));
    const uint32_t aP1 = aP0 + (2u << 10);             // +16 rows
    const uint32_t aX  = (uint32_t)((lane & 7) << 4);
    const int ka = (lane >> 4) * 8;
    // B x4 frags: quad 0: n+0..7/k+0, 1: n+0..7/k+8, 2: n+8..15/k+0, 3: n+8..15/k+8
    const int quad = lane >> 3;
    const int nb   = ((quad >> 1) << 3) + (lane & 7);
    const int kb4  = (quad & 1) << 3;
    const uint32_t bRow0 = (uint32_t)(((wq * 4 + (nb >> 3)) << 10) | ((nb & 7) << 7));
    const uint32_t bX    = (uint32_t)((lane & 7) << 4);

    const uint32_t actB = smb + SM_ACT;

    for (int t = 0; t < TILES_PER_CTA; t++) {
        const int m0 = (g * TILES_PER_CTA + t) * TILE_M;

        // ---- stage X rows for this group: [32 rows x 64 k] fp32 -> fp16 ----
        {
            const int p = wq * 32 + lane;             // 0..127 within group
            const int r = rg * 32 + (p >> 2);         // row
            const int kbx = (p & 3) << 4;             // k base
            const float4* xp = reinterpret_cast<const float4*>(x + (size_t)(m0 + r) * 64 + kbx);
            #pragma unroll
            for (int q = 0; q < 4; q++) {
                float4 v = xp[q];
                __half2 hh01 = __halves2half2(__float2half_rn(v.x), __float2half_rn(v.y));
                __half2 hh23 = __halves2half2(__float2half_rn(v.z), __float2half_rn(v.w));
                uint32_t off0 = swz(toff(r, kbx + 4 * q));
                uint32_t off1 = swz(toff(r, kbx + 4 * q + 2));
                *reinterpret_cast<uint32_t*>(smc + SM_ACT + off0) = *reinterpret_cast<uint32_t*>(&hh01);
                *reinterpret_cast<uint32_t*>(smc + SM_ACT + off1) = *reinterpret_cast<uint32_t*>(&hh23);
            }
        }
        BARG(barid);

        // ---- 3 layers ----
        #pragma unroll
        for (int l = 0; l < 3; l++) {
            float acc[2][4][4];
            #pragma unroll
            for (int mt = 0; mt < 2; mt++)
                #pragma unroll
                for (int nt = 0; nt < 4; nt++)
                    #pragma unroll
                    for (int e = 0; e < 4; e++) acc[mt][nt][e] = 0.0f;

            if (l == 0)
                layer_mma<4>(acc, actB, smb + SM_W1,  aP0, aP1, aX, ka, bRow0, bX, kb4);
            else if (l == 1)
                layer_mma<8>(acc, actB, smb + SM_WH0, aP0, aP1, aX, ka, bRow0, bX, kb4);
            else
                layer_mma<8>(acc, actB, smb + SM_WH1, aP0, aP1, aX, ka, bRow0, bX, kb4);

            if (l < 2) {
                BARG(barid);   // group done reading act before rewriting it
                const float* bias = sbias + l * 128;
                const int q = lane >> 2;      // row within 8-row block
                #pragma unroll
                for (int mt = 0; mt < 2; mt++) {
                    const uint32_t rp0 = (uint32_t)(((rg * 4 + mt * 2) << 10) | (q << 7));
                    const uint32_t rp1 = rp0 + (1u << 10);
                    #pragma unroll
                    for (int nt = 0; nt < 4; nt++) {
                        const int cc = wq * 32 + nt * 8 + (lane & 3) * 2;
                        const float b0v = bias[cc], b1v = bias[cc + 1];
                        float s0 = swishf(acc[mt][nt][0] + b0v);
                        float s1 = swishf(acc[mt][nt][1] + b1v);
                        float s2 = swishf(acc[mt][nt][2] + b0v);
                        float s3 = swishf(acc[mt][nt][3] + b1v);
                        __half2 hh01 = __halves2half2(__float2half_rn(s0), __float2half_rn(s1));
                        __half2 hh23 = __halves2half2(__float2half_rn(s2), __float2half_rn(s3));
                        const uint32_t kx = (uint32_t)(((cc >> 6) << 14) +
                                            (((cc & 63) << 1) ^ (q << 4)));
                        *reinterpret_cast<uint32_t*>(smc + SM_ACT + rp0 + kx) = *reinterpret_cast<uint32_t*>(&hh01);
                        *reinterpret_cast<uint32_t*>(smc + SM_ACT + rp1 + kx) = *reinterpret_cast<uint32_t*>(&hh23);
                    }
                }
                BARG(barid);   // writes visible before next layer's reads
            } else {
                // fused scalar head
                float ps[4] = {0.f, 0.f, 0.f, 0.f};
                #pragma unroll
                for (int mt = 0; mt < 2; mt++) {
                    #pragma unroll
                    for (int nt = 0; nt < 4; nt++) {
                        const int cc = wq * 32 + nt * 8 + (lane & 3) * 2;
                        const float b0v = sbias[256 + cc], b1v = sbias[256 + cc + 1];
                        const float w0 = sWo[cc], w1 = sWo[cc + 1];
                        ps[mt * 2 + 0] += swishf(acc[mt][nt][0] + b0v) * w0
                                        + swishf(acc[mt][nt][1] + b1v) * w1;
                        ps[mt * 2 + 1] += swishf(acc[mt][nt][2] + b0v) * w0
                                        + swishf(acc[mt][nt][3] + b1v) * w1;
                    }
                }
                #pragma unroll
                for (int i = 0; i < 4; i++) {
                    ps[i] += __shfl_xor_sync(0xffffffffu, ps[i], 1);
                    ps[i] += __shfl_xor_sync(0xffffffffu, ps[i], 2);
                }
                if ((lane & 3) == 0) {
                    const int r = lane >> 2;              // 0..7
                    float* sp = sPart + rg * 128 + wq * 32;
                    sp[r]      = ps[0];   // rows r      (mt=0)
                    sp[r + 8]  = ps[1];   // rows r+8
                    sp[r + 16] = ps[2];   // rows r+16   (mt=1)
                    sp[r + 24] = ps[3];   // rows r+24
                }
                BARG(barid);
                if (wq == 0) {
                    const float* sp = sPart + rg * 128;
                    float v = sp[lane] + sp[32 + lane] + sp[64 + lane] + sp[96 + lane];
                    out[(size_t)(m0 + rg * 32 + lane) * 32 + o] = v + bo_v;
                }
            }
        }
    }
}

extern "C" void kernel_launch(void* const* d_in, const int* in_sizes, int n_in,
                              void* d_out, int out_size) {
    const float* x  = (const float*)d_in[0];
    const float* W1 = (const float*)d_in[1];
    const float* b1 = (const float*)d_in[2];
    const float* Wh = (const float*)d_in[3];
    const float* bh = (const float*)d_in[4];
    const float* Wo = (const float*)d_in[5];
    const float* bo = (const float*)d_in[6];
    float* out = (float*)d_out;

    cudaFuncSetAttribute(mlp_fused_kernel,
                         cudaFuncAttributeMaxDynamicSharedMemorySize, SM_TOTAL);
    mlp_fused_kernel<<<GROUPS * 32, THREADS, SM_TOTAL>>>(x, W1, b1, Wh, bh, Wo, bo, out);
}

// round 6
// speedup vs baseline: 2.5586x; 1.0331x over previous
#include <cuda_runtime.h>
#include <cuda_fp16.h>
#include <cstdint>

// ============================================================
// SparseModel: 32 MLPs (64 -> 128 -> 128 -> 128 -> 1, swish)
// HMMA fp16 single-pass, warp tile 32x32, 16 warps = 4 row-groups x 4 col-quarters.
// Double-buffered activation tile: 4 barriers/tile, epilogue overlaps MMA.
// ============================================================

#define THREADS 512
#define TILE_M 128
#define GROUPS 32
#define TILES_PER_CTA 8

// ---- smem layout ----
static constexpr int SM_ACT0  = 0;        // act buf0 [128 x 128 fp16] swizzled
static constexpr int SM_ACT1  = 32768;    // act buf1
static constexpr int SM_W1    = 65536;    // W1  [128n x 64k fp16]
static constexpr int SM_WH0   = 81920;    // Wh0 [128n x 128k fp16]
static constexpr int SM_WH1   = 114688;
static constexpr int SM_PART  = 147456;          // 512 floats
static constexpr int SM_BIAS  = SM_PART + 2048;  // 3 x 128 floats
static constexpr int SM_WO    = SM_BIAS + 1536;  // 128 floats
static constexpr int SM_TOTAL = SM_WO + 512;     // 151552

// ---- helpers ----
__device__ __forceinline__ uint32_t smem_to_u32(const void* p) {
    uint32_t a;
    asm("{ .reg .u64 t; cvta.to.shared.u64 t, %1; cvt.u32.u64 %0, t; }" : "=r"(a) : "l"(p));
    return a;
}
__device__ __forceinline__ uint32_t swz(uint32_t b) { return b ^ ((b >> 3) & 0x70u); }
__device__ __forceinline__ uint32_t toff(int r, int k) {
    return (uint32_t)(((((k >> 6) << 4) + (r >> 3)) << 10) | ((r & 7) << 7) | ((k & 63) << 1));
}

#define LDSM_X4(r, addr) \
    asm volatile("ldmatrix.sync.aligned.m8n8.x4.shared.b16 {%0,%1,%2,%3}, [%4];" \
        : "=r"((r)[0]), "=r"((r)[1]), "=r"((r)[2]), "=r"((r)[3]) : "r"(addr))
#define MMA16816(d, a, b) \
    asm volatile("mma.sync.aligned.m16n8k16.row.col.f32.f16.f16.f32 " \
        "{%0,%1,%2,%3}, {%4,%5,%6,%7}, {%8,%9}, {%0,%1,%2,%3};" \
        : "+f"((d)[0]), "+f"((d)[1]), "+f"((d)[2]), "+f"((d)[3]) \
        : "r"((a)[0]), "r"((a)[1]), "r"((a)[2]), "r"((a)[3]), "r"((b)[0]), "r"((b)[1]))
#define BARG(id) asm volatile("bar.sync %0, 128;" :: "r"(id) : "memory")

__device__ __forceinline__ float swishf(float v) {
    return __fdividef(v, 1.0f + __expf(-v));
}

// fully-unrolled layer mainloop; acc[mt][nt][e]
template <int NCH>
__device__ __forceinline__ void layer_mma(
    float acc[2][4][4], uint32_t actB, uint32_t wB,
    uint32_t aP0, uint32_t aP1, uint32_t aX, int ka,
    uint32_t bRow0, uint32_t bX, int kb4)
{
    #pragma unroll
    for (int c = 0; c < NCH; ++c) {
        const uint32_t kA  = (uint32_t)(c * 16 + ka);
        const uint32_t kxA = ((kA >> 6) << 14) + (((kA & 63) << 1) ^ aX);
        const uint32_t kB  = (uint32_t)(c * 16 + kb4);
        const uint32_t kxB = ((kB >> 6) << 14) + (((kB & 63) << 1) ^ bX);

        uint32_t a0[4], a1[4], bf[4][2];
        LDSM_X4(a0, actB + aP0 + kxA);
        LDSM_X4(a1, actB + aP1 + kxA);
        #pragma unroll
        for (int np = 0; np < 2; np++) {
            uint32_t q4[4];
            LDSM_X4(q4, wB + bRow0 + ((uint32_t)np << 11) + kxB);
            bf[2*np][0]   = q4[0]; bf[2*np][1]   = q4[1];
            bf[2*np+1][0] = q4[2]; bf[2*np+1][1] = q4[3];
        }
        #pragma unroll
        for (int nt = 0; nt < 4; nt++) {
            MMA16816(acc[0][nt], a0, bf[nt]);
            MMA16816(acc[1][nt], a1, bf[nt]);
        }
    }
}

__global__ void __launch_bounds__(THREADS, 1)
mlp_fused_kernel(const float* __restrict__ x,  const float* __restrict__ W1,
                 const float* __restrict__ b1, const float* __restrict__ Wh,
                 const float* __restrict__ bh, const float* __restrict__ Wo,
                 const float* __restrict__ bo, float* __restrict__ out)
{
    extern __shared__ char smc[];
    const uint32_t smb = smem_to_u32(smc);
    const int tid = threadIdx.x;
    const int wid = tid >> 5;
    const int lane = tid & 31;
    const int o = blockIdx.x & 31;       // subnet
    const int g = blockIdx.x >> 5;       // row group of 1024 rows

    const int rg = wid >> 2;             // row group (32 rows)
    const int wq = wid & 3;              // column quarter (32 cols)
    const int barid = 1 + rg;            // named barriers 1..4 (128 threads each)

    // ---- stage weights (fp16, single rounding) ----
    {
        const float* W1p = W1 + o * 64 * 128;
        for (int idx = tid; idx < 64 * 128; idx += THREADS) {
            int k = idx >> 7, j = idx & 127;         // W1[o][k][j] -> B[n=j][k]
            *reinterpret_cast<__half*>(smc + SM_W1 + swz(toff(j, k))) = __float2half_rn(W1p[idx]);
        }
        #pragma unroll
        for (int l = 0; l < 2; l++) {
            const float* Wp = Wh + ((size_t)l * 32 + o) * 128 * 128;
            const int base = l ? SM_WH1 : SM_WH0;
            for (int idx = tid; idx < 128 * 128; idx += THREADS) {
                int k = idx >> 7, j = idx & 127;
                *reinterpret_cast<__half*>(smc + base + swz(toff(j, k))) = __float2half_rn(Wp[idx]);
            }
        }
        for (int j = tid; j < 128; j += THREADS) {
            reinterpret_cast<float*>(smc + SM_BIAS)[j]       = b1[o * 128 + j];
            reinterpret_cast<float*>(smc + SM_BIAS)[128 + j] = bh[(size_t)o * 128 + j];
            reinterpret_cast<float*>(smc + SM_BIAS)[256 + j] = bh[((size_t)32 + o) * 128 + j];
            reinterpret_cast<float*>(smc + SM_WO)[j]         = Wo[o * 128 + j];
        }
    }
    __syncthreads();

    const float bo_v   = bo[o];
    const float* sbias = reinterpret_cast<const float*>(smc + SM_BIAS);
    const float* sWo   = reinterpret_cast<const float*>(smc + SM_WO);
    float* sPart       = reinterpret_cast<float*>(smc + SM_PART);

    // ---- ldmatrix lane addressing ----
    const int ra0 = rg * 32 + ((lane >> 3) & 1) * 8 + (lane & 7);
    const uint32_t aP0 = (uint32_t)(((ra0 >> 3) << 10) | ((ra0 & 7) << 7));
    const uint32_t aP1 = aP0 + (2u << 10);             // +16 rows
    const uint32_t aX  = (uint32_t)((lane & 7) << 4);
    const int ka = (lane >> 4) * 8;
    const int quad = lane >> 3;
    const int nb   = ((quad >> 1) << 3) + (lane & 7);
    const int kb4  = (quad & 1) << 3;
    const uint32_t bRow0 = (uint32_t)(((wq * 4 + (nb >> 3)) << 10) | ((nb & 7) << 7));
    const uint32_t bX    = (uint32_t)((lane & 7) << 4);

    const uint32_t act0 = smb + SM_ACT0;
    const uint32_t act1 = smb + SM_ACT1;
    // epilogue addressing (same for both buffers; add buffer base)
    const int q = lane >> 2;

    for (int t = 0; t < TILES_PER_CTA; t++) {
        const int m0 = (g * TILES_PER_CTA + t) * TILE_M;

        // ---- stage X rows for this group: [32 rows x 64 k] fp32 -> fp16 -> buf0 ----
        {
            const int p = wq * 32 + lane;             // 0..127 within group
            const int r = rg * 32 + (p >> 2);         // row
            const int kbx = (p & 3) << 4;             // k base
            const float4* xp = reinterpret_cast<const float4*>(x + (size_t)(m0 + r) * 64 + kbx);
            #pragma unroll
            for (int qq = 0; qq < 4; qq++) {
                float4 v = xp[qq];
                __half2 hh01 = __halves2half2(__float2half_rn(v.x), __float2half_rn(v.y));
                __half2 hh23 = __halves2half2(__float2half_rn(v.z), __float2half_rn(v.w));
                uint32_t off0 = swz(toff(r, kbx + 4 * qq));
                uint32_t off1 = swz(toff(r, kbx + 4 * qq + 2));
                *reinterpret_cast<uint32_t*>(smc + SM_ACT0 + off0) = *reinterpret_cast<uint32_t*>(&hh01);
                *reinterpret_cast<uint32_t*>(smc + SM_ACT0 + off1) = *reinterpret_cast<uint32_t*>(&hh23);
            }
        }
        BARG(barid);                 // (1) X visible

        // ---- layers 0 and 1: mma from src buf, epilogue to dst buf ----
        #pragma unroll
        for (int l = 0; l < 2; l++) {
            float acc[2][4][4];
            #pragma unroll
            for (int mt = 0; mt < 2; mt++)
                #pragma unroll
                for (int nt = 0; nt < 4; nt++)
                    #pragma unroll
                    for (int e = 0; e < 4; e++) acc[mt][nt][e] = 0.0f;

            const uint32_t src = (l == 0) ? act0 : act1;
            const uint32_t dstB = (l == 0) ? SM_ACT1 : SM_ACT0;
            if (l == 0)
                layer_mma<4>(acc, src, smb + SM_W1,  aP0, aP1, aX, ka, bRow0, bX, kb4);
            else
                layer_mma<8>(acc, src, smb + SM_WH0, aP0, aP1, aX, ka, bRow0, bX, kb4);

            // epilogue straight after own MMA (no pre-barrier; writes other buffer)
            const float* bias = sbias + l * 128;
            #pragma unroll
            for (int mt = 0; mt < 2; mt++) {
                const uint32_t rp0 = (uint32_t)(((rg * 4 + mt * 2) << 10) | (q << 7));
                const uint32_t rp1 = rp0 + (1u << 10);
                #pragma unroll
                for (int nt = 0; nt < 4; nt++) {
                    const int cc = wq * 32 + nt * 8 + (lane & 3) * 2;
                    const float b0v = bias[cc], b1v = bias[cc + 1];
                    float s0 = swishf(acc[mt][nt][0] + b0v);
                    float s1 = swishf(acc[mt][nt][1] + b1v);
                    float s2 = swishf(acc[mt][nt][2] + b0v);
                    float s3 = swishf(acc[mt][nt][3] + b1v);
                    __half2 hh01 = __halves2half2(__float2half_rn(s0), __float2half_rn(s1));
                    __half2 hh23 = __halves2half2(__float2half_rn(s2), __float2half_rn(s3));
                    const uint32_t kx = (uint32_t)(((cc >> 6) << 14) +
                                        (((cc & 63) << 1) ^ (q << 4)));
                    *reinterpret_cast<uint32_t*>(smc + dstB + rp0 + kx) = *reinterpret_cast<uint32_t*>(&hh01);
                    *reinterpret_cast<uint32_t*>(smc + dstB + rp1 + kx) = *reinterpret_cast<uint32_t*>(&hh23);
                }
            }
            BARG(barid);             // (2)/(3) dst visible for next layer
        }

        // ---- layer 2 + fused scalar head (reads buf0, no act writes) ----
        {
            float acc[2][4][4];
            #pragma unroll
            for (int mt = 0; mt < 2; mt++)
                #pragma unroll
                for (int nt = 0; nt < 4; nt++)
                    #pragma unroll
                    for (int e = 0; e < 4; e++) acc[mt][nt][e] = 0.0f;

            layer_mma<8>(acc, act0, smb + SM_WH1, aP0, aP1, aX, ka, bRow0, bX, kb4);

            float ps[4] = {0.f, 0.f, 0.f, 0.f};
            #pragma unroll
            for (int mt = 0; mt < 2; mt++) {
                #pragma unroll
                for (int nt = 0; nt < 4; nt++) {
                    const int cc = wq * 32 + nt * 8 + (lane & 3) * 2;
                    const float b0v = sbias[256 + cc], b1v = sbias[256 + cc + 1];
                    const float w0 = sWo[cc], w1 = sWo[cc + 1];
                    ps[mt * 2 + 0] += swishf(acc[mt][nt][0] + b0v) * w0
                                    + swishf(acc[mt][nt][1] + b1v) * w1;
                    ps[mt * 2 + 1] += swishf(acc[mt][nt][2] + b0v) * w0
                                    + swishf(acc[mt][nt][3] + b1v) * w1;
                }
            }
            #pragma unroll
            for (int i = 0; i < 4; i++) {
                ps[i] += __shfl_xor_sync(0xffffffffu, ps[i], 1);
                ps[i] += __shfl_xor_sync(0xffffffffu, ps[i], 2);
            }
            if ((lane & 3) == 0) {
                const int r = lane >> 2;              // 0..7
                float* sp = sPart + rg * 128 + wq * 32;
                sp[r]      = ps[0];
                sp[r + 8]  = ps[1];
                sp[r + 16] = ps[2];
                sp[r + 24] = ps[3];
            }
            BARG(barid);             // (4) sPart visible; also guards buf0 re-staging
            if (wq == 0) {
                const float* sp = sPart + rg * 128;
                float v = sp[lane] + sp[32 + lane] + sp[64 + lane] + sp[96 + lane];
                out[(size_t)(m0 + rg * 32 + lane) * 32 + o] = v + bo_v;
            }
        }
    }
}

extern "C" void kernel_launch(void* const* d_in, const int* in_sizes, int n_in,
                              void* d_out, int out_size) {
    const float* x  = (const float*)d_in[0];
    const float* W1 = (const float*)d_in[1];
    const float* b1 = (const float*)d_in[2];
    const float* Wh = (const float*)d_in[3];
    const float* bh = (const float*)d_in[4];
    const float* Wo = (const float*)d_in[5];
    const float* bo = (const float*)d_in[6];
    float* out = (float*)d_out;

    cudaFuncSetAttribute(mlp_fused_kernel,
                         cudaFuncAttributeMaxDynamicSharedMemorySize, SM_TOTAL);
    mlp_fused_kernel<<<GROUPS * 32, THREADS, SM_TOTAL>>>(x, W1, b1, Wh, bh, Wo, bo, out);
}